// round 8
// baseline (speedup 1.0000x reference)
#include <cuda_runtime.h>
#include <cuda_bf16.h>
#include <stdint.h>
#include <stddef.h>
#include <math.h>

#define TT 128
#define BB 32
#define VV 32000
#define EE 512
#define HH 1024
#define KK 1536          // E + H
#define GG 4096          // 4H
#define NCHUNK 250       // logits chunks of 128 vocab rows
#define STAGE 20480      // logits pipeline stage bytes (A 16K + B 4K)
#define NCTA 148

// ---------------- scratch (no allocations allowed) ----------------
__device__ __align__(16) float g_h3[3][HH * BB];        // h fp32, [k][b], triple-buffered
__device__ __align__(16) __nv_bfloat16 g_hb3[3][BB * HH]; // h bf16, [b][k], triple-buffered
__device__ __align__(16) float g_c[HH * BB];            // c[k][b]
__device__ __align__(16) __nv_bfloat16 g_wout[(size_t)VV * HH]; // W_out bf16 (64MB)
__device__ __align__(16) __nv_bfloat16 g_wperm[(size_t)GG * KK]; // permuted W_ih|W_hh bf16
__device__ __align__(16) float g_biasp[GG];             // permuted b_ih+b_hh
__device__ float2 g_part[2][NCHUNK * BB];               // (max,sumexp), double-buffered
__device__ float g_loss;
__device__ unsigned g_count;                            // grid barrier counter

// ---------------- helpers ----------------
__device__ __forceinline__ uint32_t su32(const void* p) {
    uint32_t a;
    asm("{ .reg .u64 t; cvta.to.shared.u64 t, %1; cvt.u32.u64 %0, t; }" : "=r"(a) : "l"(p));
    return a;
}
#define SWZ(o) ((o) ^ (((o) >> 3) & 0x70))

__device__ __forceinline__ void ldm_x4(uint32_t* r, uint32_t addr) {
    asm volatile("ldmatrix.sync.aligned.m8n8.x4.shared.b16 {%0,%1,%2,%3}, [%4];"
                 : "=r"(r[0]), "=r"(r[1]), "=r"(r[2]), "=r"(r[3]) : "r"(addr));
}
__device__ __forceinline__ void mma16816(float* c, const uint32_t* a, const uint32_t* b) {
    asm volatile("mma.sync.aligned.m16n8k16.row.col.f32.bf16.bf16.f32 "
                 "{%0,%1,%2,%3}, {%4,%5,%6,%7}, {%8,%9}, {%0,%1,%2,%3};"
                 : "+f"(c[0]), "+f"(c[1]), "+f"(c[2]), "+f"(c[3])
                 : "r"(a[0]), "r"(a[1]), "r"(a[2]), "r"(a[3]), "r"(b[0]), "r"(b[1]));
}
__device__ __forceinline__ uint32_t pack2(float a, float b) {
    __nv_bfloat162 p = __floats2bfloat162_rn(a, b);
    return *reinterpret_cast<uint32_t*>(&p);
}
__device__ __forceinline__ void cpa16(uint32_t dst, const void* src) {
    asm volatile("cp.async.cg.shared.global [%0], [%1], 16;" :: "r"(dst), "l"(src) : "memory");
}
#define CPA_COMMIT() asm volatile("cp.async.commit_group;" ::: "memory")
#define CPA_WAIT1()  asm volatile("cp.async.wait_group 1;" ::: "memory")
#define CPA_WAIT0()  asm volatile("cp.async.wait_group 0;" ::: "memory")

// grid-wide barrier: monotonic counter, one arrival per CTA
__device__ __forceinline__ void gridbar(unsigned target) {
    __threadfence();
    __syncthreads();
    if (threadIdx.x == 0) {
        atomicAdd(&g_count, 1u);
        while (*(volatile unsigned*)&g_count < target) { }
    }
    __syncthreads();
}

// ---------------- one-time conversions ----------------
__global__ void k_convert(const float* __restrict__ W) {
    size_t i = ((size_t)blockIdx.x * blockDim.x + threadIdx.x) * 4;
    float4 v = *(const float4*)(W + i);
    g_wout[i + 0] = __float2bfloat16(v.x);
    g_wout[i + 1] = __float2bfloat16(v.y);
    g_wout[i + 2] = __float2bfloat16(v.z);
    g_wout[i + 3] = __float2bfloat16(v.w);
}
__global__ void k_convw(const float* __restrict__ W_ih, const float* __restrict__ W_hh) {
    size_t i4 = ((size_t)blockIdx.x * blockDim.x + threadIdx.x) * 4;
    int kk = (int)(i4 % KK);
    int rr = (int)(i4 / KK);
    int j = rr >> 7, r = rr & 127;
    int srcrow = (r >> 5) * HH + j * 32 + (r & 31);
    float4 v;
    if (kk < EE) v = *(const float4*)&W_ih[(size_t)srcrow * EE + kk];
    else         v = *(const float4*)&W_hh[(size_t)srcrow * HH + (kk - EE)];
    g_wperm[i4 + 0] = __float2bfloat16(v.x);
    g_wperm[i4 + 1] = __float2bfloat16(v.y);
    g_wperm[i4 + 2] = __float2bfloat16(v.z);
    g_wperm[i4 + 3] = __float2bfloat16(v.w);
}
__global__ void k_convb(const float* __restrict__ b_ih, const float* __restrict__ b_hh) {
    int id = blockIdx.x * blockDim.x + threadIdx.x;
    int j = id >> 7, r = id & 127;
    int srcrow = (r >> 5) * HH + j * 32 + (r & 31);
    g_biasp[id] = b_ih[srcrow] + b_hh[srcrow];
}
__global__ void k_init(const float* __restrict__ h0, const float* __restrict__ c0) {
    int i = blockIdx.x * blockDim.x + threadIdx.x;
    if (i < HH * BB) {
        int b = i / HH, k = i % HH;
        g_h3[0][k * BB + b] = h0[i];
        g_c[k * BB + b] = c0[i];
        g_hb3[0][i] = __float2bfloat16(h0[i]);
    }
    if (i == 0) { g_loss = 0.f; g_count = 0u; }
}

// ---------------- gates GEMM + LSTM (device) ----------------
// Computes h(s+1): reads h buf s%3 (via L2), c (CTA-private); writes buf (s+1)%3, c.
__device__ void gates_dev(const int* __restrict__ indices, const float* __restrict__ emb,
                          int s, int jj, char* sbuf) {
    const int tid = threadIdx.x;
    const int w = tid >> 5, lane = tid & 31;
    const uint32_t sbA = su32(sbuf);
    const uint32_t sbB = sbA + 16384u;
    const __nv_bfloat16* hbin = g_hb3[s % 3];
    const int out = (s + 1) % 3;

    const char* wbase = (const char*)(g_wperm + (size_t)jj * 128 * KK);
    const int arow[4] = { (tid + 0) >> 3, (tid + 256) >> 3, (tid + 512) >> 3, (tid + 768) >> 3 };
    const int ac = tid & 7;
    const int brow = tid >> 3, bc = tid & 7;
    const int myidx = indices[s * BB + brow];

    float c[16];
    #pragma unroll
    for (int i = 0; i < 16; i++) c[i] = 0.f;

    float4 ra[4];
    uint4 rb;
    #pragma unroll
    for (int i = 0; i < 4; i++)
        ra[i] = *(const float4*)(wbase + ((size_t)arow[i] * KK + ac * 8) * 2);
    {
        const float* e = emb + (size_t)myidx * EE + bc * 8;
        float4 v0 = *(const float4*)e, v1 = *(const float4*)(e + 4);
        rb.x = pack2(fmaxf(v0.x, 0.f), fmaxf(v0.y, 0.f));
        rb.y = pack2(fmaxf(v0.z, 0.f), fmaxf(v0.w, 0.f));
        rb.z = pack2(fmaxf(v1.x, 0.f), fmaxf(v1.y, 0.f));
        rb.w = pack2(fmaxf(v1.z, 0.f), fmaxf(v1.w, 0.f));
    }

    const int lr = lane & 15, lcs = (lane >> 4) << 3;
    const int bn = (lane & 7) + ((lane >> 4) << 3);
    const int bko = ((lane >> 3) & 1) << 3;

    for (int ch = 0; ch < 24; ch++) {
        __syncthreads();
        #pragma unroll
        for (int i = 0; i < 4; i++)
            *(float4*)(sbuf + SWZ(arow[i] * 128 + ac * 16)) = ra[i];
        *(uint4*)(sbuf + 16384 + SWZ(brow * 128 + bc * 16)) = rb;
        __syncthreads();

        if (ch < 23) {
            int ko = (ch + 1) * 64;
            #pragma unroll
            for (int i = 0; i < 4; i++)
                ra[i] = *(const float4*)(wbase + ((size_t)arow[i] * KK + ko + ac * 8) * 2);
            if (ko < EE) {
                const float* e = emb + (size_t)myidx * EE + ko + bc * 8;
                float4 v0 = *(const float4*)e, v1 = *(const float4*)(e + 4);
                rb.x = pack2(fmaxf(v0.x, 0.f), fmaxf(v0.y, 0.f));
                rb.y = pack2(fmaxf(v0.z, 0.f), fmaxf(v0.w, 0.f));
                rb.z = pack2(fmaxf(v1.x, 0.f), fmaxf(v1.y, 0.f));
                rb.w = pack2(fmaxf(v1.z, 0.f), fmaxf(v1.w, 0.f));
            } else {
                rb = __ldcg((const uint4*)((const char*)hbin + ((size_t)brow * HH + ko - EE + bc * 8) * 2));
            }
        }

        #pragma unroll
        for (int s4 = 0; s4 < 4; s4++) {
            uint32_t a[4], b01[4], b23[4];
            ldm_x4(a,   sbA + SWZ((w * 16 + lr) * 128 + (s4 * 16 + lcs) * 2));
            ldm_x4(b01, sbB + SWZ(bn * 128 + (s4 * 16 + bko) * 2));
            ldm_x4(b23, sbB + SWZ((bn + 16) * 128 + (s4 * 16 + bko) * 2));
            mma16816(c + 0,  a, b01 + 0);
            mma16816(c + 4,  a, b01 + 2);
            mma16816(c + 8,  a, b23 + 0);
            mma16816(c + 12, a, b23 + 2);
        }
    }
    __syncthreads();

    float* sl = (float*)sbuf;
    {
        int r0 = w * 16 + (lane >> 2);
        float bias0 = g_biasp[jj * 128 + r0];
        float bias1 = g_biasp[jj * 128 + r0 + 8];
        #pragma unroll
        for (int g = 0; g < 4; g++) {
            int col = g * 8 + 2 * (lane & 3);
            sl[r0 * 33 + col]           = c[g * 4 + 0] + bias0;
            sl[r0 * 33 + col + 1]       = c[g * 4 + 1] + bias0;
            sl[(r0 + 8) * 33 + col]     = c[g * 4 + 2] + bias1;
            sl[(r0 + 8) * 33 + col + 1] = c[g * 4 + 3] + bias1;
        }
    }
    __syncthreads();
    {
        int hu = tid >> 3;
        int b0 = (tid & 7) * 4;
        int k = jj * 32 + hu;
        #pragma unroll
        for (int q = 0; q < 4; q++) {
            int b = b0 + q;
            float ig = sl[hu * 33 + b];
            float fg = sl[(32 + hu) * 33 + b];
            float gg = sl[(64 + hu) * 33 + b];
            float og = sl[(96 + hu) * 33 + b];
            float si = 1.f / (1.f + expf(-ig));
            float sf = 1.f / (1.f + expf(-fg));
            float so = 1.f / (1.f + expf(-og));
            float cn = sf * g_c[k * BB + b] + si * tanhf(gg);
            g_c[k * BB + b] = cn;
            float h = so * tanhf(cn);
            g_h3[out][k * BB + b] = h;
            g_hb3[out][b * HH + k] = __float2bfloat16(h);
        }
    }
    __syncthreads();   // smem free before next use
}

// ---------------- logits chunk (device, 3-stage cp.async) ----------------
// logits(t) for vocab chunk cc: reads h buf (t+1)%3, writes g_part[t&1][cc*BB..].
__device__ void logits_chunk(const float* __restrict__ b_out, int t, int cc, char* sbuf,
                             float (*redM)[32], float (*redS)[32]) {
    const int tid = threadIdx.x;
    const int w = tid >> 5, lane = tid & 31;
    const int v0 = cc * 128;
    const uint32_t sb = su32(sbuf);

    const char* wbase = (const char*)(g_wout + (size_t)v0 * HH);
    const char* hbase = (const char*)g_hb3[(t + 1) % 3];

    const int arow[4] = { (tid + 0) >> 3, (tid + 256) >> 3, (tid + 512) >> 3, (tid + 768) >> 3 };
    const int ac = tid & 7;
    const int brow = tid >> 3, bc = tid & 7;

    uint32_t dA[4];
    #pragma unroll
    for (int i = 0; i < 4; i++) dA[i] = SWZ(arow[i] * 128 + ac * 16);
    const uint32_t dB = 16384u + SWZ(brow * 128 + bc * 16);

    #define ISSUE(st, ch) do { \
        uint32_t base = sb + (st) * STAGE; \
        _Pragma("unroll") \
        for (int i = 0; i < 4; i++) \
            cpa16(base + dA[i], wbase + ((size_t)arow[i] * HH + (ch) * 64 + ac * 8) * 2); \
        cpa16(base + dB, hbase + ((size_t)brow * HH + (ch) * 64 + bc * 8) * 2); \
        CPA_COMMIT(); \
    } while (0)

    ISSUE(0, 0);
    ISSUE(1, 1);

    float c[16];
    #pragma unroll
    for (int i = 0; i < 16; i++) c[i] = 0.f;

    const int lr = lane & 15, lcs = (lane >> 4) << 3;
    const int bn = (lane & 7) + ((lane >> 4) << 3);
    const int bko = ((lane >> 3) & 1) << 3;

    for (int ch = 0; ch < 16; ch++) {
        if (ch == 15) CPA_WAIT0(); else CPA_WAIT1();
        __syncthreads();
        if (ch < 14) ISSUE((ch + 2) % 3, ch + 2);

        uint32_t sA = sb + (ch % 3) * STAGE;
        uint32_t sB = sA + 16384u;
        #pragma unroll
        for (int s4 = 0; s4 < 4; s4++) {
            uint32_t a[4], b01[4], b23[4];
            ldm_x4(a,   sA + SWZ((w * 16 + lr) * 128 + (s4 * 16 + lcs) * 2));
            ldm_x4(b01, sB + SWZ(bn * 128 + (s4 * 16 + bko) * 2));
            ldm_x4(b23, sB + SWZ((bn + 16) * 128 + (s4 * 16 + bko) * 2));
            mma16816(c + 0,  a, b01 + 0);
            mma16816(c + 4,  a, b01 + 2);
            mma16816(c + 8,  a, b23 + 0);
            mma16816(c + 12, a, b23 + 2);
        }
    }
    #undef ISSUE
    __syncthreads();

    float* sl = (float*)sbuf;
    {
        int r0 = w * 16 + (lane >> 2);
        float bias0 = b_out[v0 + r0];
        float bias1 = b_out[v0 + r0 + 8];
        #pragma unroll
        for (int g = 0; g < 4; g++) {
            int col = g * 8 + 2 * (lane & 3);
            sl[r0 * 33 + col]           = c[g * 4 + 0] + bias0;
            sl[r0 * 33 + col + 1]       = c[g * 4 + 1] + bias0;
            sl[(r0 + 8) * 33 + col]     = c[g * 4 + 2] + bias1;
            sl[(r0 + 8) * 33 + col + 1] = c[g * 4 + 3] + bias1;
        }
    }
    __syncthreads();

    if (tid < 128) {
        int q = tid >> 5, b = tid & 31;
        float M = -1e30f, S = 0.f;
        #pragma unroll
        for (int r = 0; r < 32; r++) {
            float l = sl[(q * 32 + r) * 33 + b];
            if (l > M) { S = S * expf(M - l) + 1.f; M = l; }
            else       { S += expf(l - M); }
        }
        redM[q][b] = M; redS[q][b] = S;
    }
    __syncthreads();
    if (tid < 32) {
        float M = -1e30f, S = 0.f;
        #pragma unroll
        for (int q = 0; q < 4; q++) {
            float m2 = redM[q][tid], s2 = redS[q][tid];
            if (m2 > M) { S = S * expf(M - m2) + s2; M = m2; }
            else        { S += s2 * expf(m2 - M); }
        }
        g_part[t & 1][cc * BB + tid] = make_float2(M, S);
    }
    __syncthreads();   // smem free before next use
}

// ---------------- merge (device, 256 threads); returns step nll sum at tid 0 ----------------
__device__ float merge_dev(const int* __restrict__ indices, const float* __restrict__ W_out,
                           const float* __restrict__ b_out, int tau, float* nll) {
    const int tid = threadIdx.x;
    const int wid = tid >> 5, l = tid & 31;
    const float2* part = g_part[tau & 1];
    const float* hfp = g_h3[(tau + 1) % 3];

    for (int b = wid; b < 32; b += 8) {
        float M = -1e30f;
        for (int c = l; c < NCHUNK; c += 32) M = fmaxf(M, __ldcg(&part[c * BB + b]).x);
        #pragma unroll
        for (int o = 16; o; o >>= 1) M = fmaxf(M, __shfl_xor_sync(0xFFFFFFFFu, M, o));
        float S = 0.f;
        for (int c = l; c < NCHUNK; c += 32) {
            float2 p = __ldcg(&part[c * BB + b]);
            S += p.y * expf(p.x - M);
        }
        #pragma unroll
        for (int o = 16; o; o >>= 1) S += __shfl_xor_sync(0xFFFFFFFFu, S, o);
        int tgt = indices[(tau + 1) * BB + b];
        float z = 0.f;
        for (int e = l; e < HH; e += 32) z += __ldcg(&hfp[e * BB + b]) * W_out[(size_t)tgt * HH + e];
        #pragma unroll
        for (int o = 16; o; o >>= 1) z += __shfl_xor_sync(0xFFFFFFFFu, z, o);
        if (l == 0) nll[b] = (tgt != 0) ? (logf(S) + M - (z + b_out[tgt])) : 0.f;
    }
    __syncthreads();
    float r = 0.f;
    if (tid == 0) {
        #pragma unroll
        for (int b = 0; b < 32; b++) r += nll[b];
    }
    __syncthreads();
    return r;
}

// ---------------- persistent whole-scan kernel ----------------
// 148 CTAs, 1/SM. Per step t: CTA c<102 -> logits chunks c & c+148; 102-133 ->
// chunk c + gates tile (c-102); 134-146 -> chunk c; 147 -> chunk 147 + merge(t-1).
__global__ void __launch_bounds__(256) k_scan(const int* __restrict__ indices,
                                              const float* __restrict__ emb,
                                              const float* __restrict__ W_out,
                                              const float* __restrict__ b_out) {
    extern __shared__ char sbuf[];
    __shared__ float redM[4][32], redS[4][32];
    __shared__ float nll[32];
    const int cta = blockIdx.x;
    unsigned barn = 0;
    float loss_acc = 0.f;

    // h(1) before the loop
    if (cta >= 102 && cta < 134) gates_dev(indices, emb, 0, cta - 102, sbuf);
    barn++; gridbar(NCTA * barn);

    for (int t = 0; t < TT - 1; t++) {
        logits_chunk(b_out, t, cta, sbuf, redM, redS);
        if (cta < 102) {
            logits_chunk(b_out, t, cta + 148, sbuf, redM, redS);
        } else if (cta < 134) {
            if (t <= TT - 3) gates_dev(indices, emb, t + 1, cta - 102, sbuf);
        } else if (cta == 147) {
            if (t >= 1) loss_acc += merge_dev(indices, W_out, b_out, t - 1, nll);
        }
        barn++; gridbar(NCTA * barn);
    }
    if (cta == 147) {
        loss_acc += merge_dev(indices, W_out, b_out, TT - 2, nll);
        if (threadIdx.x == 0) g_loss = loss_acc;
    }
}

__global__ void k_out(float* out, int n) {
    int i = blockIdx.x * blockDim.x + threadIdx.x;
    if (i < n) out[i] = (i == 0) ? g_loss : 0.f;
}

// ---------------- launch ----------------
extern "C" void kernel_launch(void* const* d_in, const int* in_sizes, int n_in,
                              void* d_out, int out_size) {
    const int*   indices = (const int*)d_in[0];
    const float* emb     = (const float*)d_in[1];
    const float* W_ih    = (const float*)d_in[2];
    const float* W_hh    = (const float*)d_in[3];
    const float* b_ih    = (const float*)d_in[4];
    const float* b_hh    = (const float*)d_in[5];
    const float* W_out   = (const float*)d_in[6];
    const float* b_out   = (const float*)d_in[7];
    const float* h0      = (const float*)d_in[8];
    const float* c0      = (const float*)d_in[9];

    cudaFuncSetAttribute(k_scan, cudaFuncAttributeMaxDynamicSharedMemorySize, 3 * STAGE);

    k_convert<<<(VV * HH / 4) / 256, 256>>>(W_out);
    k_convw<<<(GG * KK / 4) / 256, 256>>>(W_ih, W_hh);
    k_convb<<<GG / 256, 256>>>(b_ih, b_hh);
    k_init<<<(HH * BB + 255) / 256, 256>>>(h0, c0);

    k_scan<<<NCTA, 256, 3 * STAGE>>>(indices, emb, W_out, b_out);
    k_out<<<(out_size + 255) / 256, 256>>>((float*)d_out, out_size);
}

// round 9
// speedup vs baseline: 1.1664x; 1.1664x over previous
#include <cuda_runtime.h>
#include <cuda_bf16.h>
#include <stdint.h>
#include <stddef.h>
#include <math.h>

#define TT 128
#define BB 32
#define VV 32000
#define EE 512
#define HH 1024
#define KK 1536
#define GG 4096
#define NCHUNK 250       // logits chunks of 128 vocab rows
#define STAGE 20480      // stage bytes: A 16K + B 4K
#define LCH 8            // logits K-chunks of 128 int8
#define GCH 12           // gates K-chunks of 128 int8

// ---------------- scratch ----------------
__device__ __align__(16) float g_h3[3][HH * BB];          // h fp32 [k][b]
__device__ __align__(16) signed char g_hq3[3][BB * HH];   // h int8 [b][k], scale 1/127
__device__ __align__(16) float g_c[HH * BB];              // c[k][b]
__device__ __align__(16) signed char g_wq[(size_t)VV * HH];   // W_out int8 (32MB)
__device__ __align__(16) float g_fsw[VV];                 // rowmax/(127*127)
__device__ __align__(16) signed char g_wqg[(size_t)GG * KK];  // gates W int8, permuted+col-scaled
__device__ __align__(16) float g_sg[GG];                  // per-row scale
__device__ __align__(16) float g_biasp[GG];               // permuted b_ih+b_hh
__device__ __align__(16) signed char g_xq[(TT - 1) * BB * EE]; // x int8, all steps (2MB)
__device__ unsigned g_xmax = 0u;                          // max relu(emb) as uint bits
__device__ float2 g_part[2][NCHUNK * BB];
__device__ float g_loss;

// ---------------- helpers ----------------
__device__ __forceinline__ uint32_t su32(const void* p) {
    uint32_t a;
    asm("{ .reg .u64 t; cvta.to.shared.u64 t, %1; cvt.u32.u64 %0, t; }" : "=r"(a) : "l"(p));
    return a;
}
#define SWZ(o) ((o) ^ (((o) >> 3) & 0x70))

__device__ __forceinline__ void ldm_x4(uint32_t* r, uint32_t addr) {
    asm volatile("ldmatrix.sync.aligned.m8n8.x4.shared.b16 {%0,%1,%2,%3}, [%4];"
                 : "=r"(r[0]), "=r"(r[1]), "=r"(r[2]), "=r"(r[3]) : "r"(addr));
}
__device__ __forceinline__ void imma16832(int* c, const uint32_t* a, const uint32_t* b) {
    asm volatile("mma.sync.aligned.m16n8k32.row.col.s32.s8.s8.s32 "
                 "{%0,%1,%2,%3}, {%4,%5,%6,%7}, {%8,%9}, {%0,%1,%2,%3};"
                 : "+r"(c[0]), "+r"(c[1]), "+r"(c[2]), "+r"(c[3])
                 : "r"(a[0]), "r"(a[1]), "r"(a[2]), "r"(a[3]), "r"(b[0]), "r"(b[1]));
}
__device__ __forceinline__ void cpa16(uint32_t dst, const void* src) {
    asm volatile("cp.async.cg.shared.global [%0], [%1], 16;" :: "r"(dst), "l"(src) : "memory");
}
#define CPA_COMMIT() asm volatile("cp.async.commit_group;" ::: "memory")
#define CPA_WAIT1()  asm volatile("cp.async.wait_group 1;" ::: "memory")
#define CPA_WAIT0()  asm volatile("cp.async.wait_group 0;" ::: "memory")

__device__ __forceinline__ signed char q8(float v) {
    int x = __float2int_rn(v);
    x = x > 127 ? 127 : (x < -127 ? -127 : x);
    return (signed char)x;
}

// ---------------- setup 1: W_out -> int8 per-row; emb max ----------------
__global__ void k_setup1(const float* __restrict__ W, const float* __restrict__ emb) {
    int wid = blockIdx.x * 8 + (threadIdx.x >> 5);   // vocab row, 4000 CTAs x 8 warps
    int lane = threadIdx.x & 31;
    const float* row = W + (size_t)wid * HH;
    float m = 0.f;
    #pragma unroll
    for (int i = 0; i < 32; i++) m = fmaxf(m, fabsf(row[lane + 32 * i]));
    #pragma unroll
    for (int o = 16; o; o >>= 1) m = fmaxf(m, __shfl_xor_sync(0xFFFFFFFFu, m, o));
    float inv = (m > 1e-30f) ? 127.f / m : 0.f;
    if (lane == 0) g_fsw[wid] = m / (127.f * 127.f);
    signed char* dst = g_wq + (size_t)wid * HH;
    #pragma unroll
    for (int i = 0; i < 32; i++) {
        int k = lane + 32 * i;
        dst[k] = q8(row[k] * inv);
    }
    // emb positive max (relu range); deterministic atomicMax on positive-float bits
    size_t gtid = (size_t)blockIdx.x * blockDim.x + threadIdx.x;
    size_t n = (size_t)VV * EE, nt = (size_t)gridDim.x * blockDim.x;
    float em = 0.f;
    for (size_t i = gtid; i < n; i += nt) em = fmaxf(em, emb[i]);
    #pragma unroll
    for (int o = 16; o; o >>= 1) em = fmaxf(em, __shfl_xor_sync(0xFFFFFFFFu, em, o));
    if (lane == 0 && em > 0.f) atomicMax(&g_xmax, __float_as_uint(em));
}

// ---------------- setup 2: gates W permute + col-scale + per-row int8 ----------------
__global__ void k_setup2(const float* __restrict__ W_ih, const float* __restrict__ W_hh,
                         const float* __restrict__ b_ih, const float* __restrict__ b_hh) {
    int id = blockIdx.x * 8 + (threadIdx.x >> 5);   // permuted row, 512 CTAs x 8 warps
    int lane = threadIdx.x & 31;
    int j = id >> 7, r = id & 127;
    int srcrow = (r >> 5) * HH + j * 32 + (r & 31);
    float s_x = __uint_as_float(g_xmax) / 127.f;
    const float sh = 1.f / 127.f;
    float m = 0.f;
    #pragma unroll
    for (int i = 0; i < 48; i++) {
        int k = lane + 32 * i;
        float w = (k < EE) ? W_ih[(size_t)srcrow * EE + k] * s_x
                           : W_hh[(size_t)srcrow * HH + (k - EE)] * sh;
        m = fmaxf(m, fabsf(w));
    }
    #pragma unroll
    for (int o = 16; o; o >>= 1) m = fmaxf(m, __shfl_xor_sync(0xFFFFFFFFu, m, o));
    float inv = (m > 1e-30f) ? 127.f / m : 0.f;
    if (lane == 0) { g_sg[id] = m / 127.f; g_biasp[id] = b_ih[srcrow] + b_hh[srcrow]; }
    signed char* dst = g_wqg + (size_t)id * KK;
    #pragma unroll
    for (int i = 0; i < 48; i++) {
        int k = lane + 32 * i;
        float w = (k < EE) ? W_ih[(size_t)srcrow * EE + k] * s_x
                           : W_hh[(size_t)srcrow * HH + (k - EE)] * sh;
        dst[k] = q8(w * inv);
    }
}

// ---------------- setup 3: x int8 for all steps + state init ----------------
__global__ void k_setup3(const int* __restrict__ indices, const float* __restrict__ emb,
                         const float* __restrict__ h0, const float* __restrict__ c0) {
    if (blockIdx.x < 508) {
        int tb = blockIdx.x * 8 + (threadIdx.x >> 5);   // (t,b) pair, 4064 warps
        int lane = threadIdx.x & 31;
        if (tb < (TT - 1) * BB) {
            int idx = indices[tb];
            float inv = 127.f / __uint_as_float(g_xmax);
            const float* e = emb + (size_t)idx * EE;
            signed char* dst = g_xq + (size_t)tb * EE;
            #pragma unroll
            for (int i = 0; i < 16; i++) {
                int k = lane + 32 * i;
                dst[k] = q8(fmaxf(e[k], 0.f) * inv);
            }
        }
    } else {
        int i = (blockIdx.x - 508) * 256 + threadIdx.x;
        if (i < HH * BB) {
            int b = i / HH, k = i % HH;
            g_h3[0][k * BB + b] = h0[i];
            g_c[k * BB + b] = c0[i];
            g_hq3[0][i] = q8(h0[i] * 127.f);
        }
        if (blockIdx.x == 508 && threadIdx.x == 0) g_loss = 0.f;
    }
}

// ---------------- gates int8 GEMM + LSTM ----------------
// computes h(s+1): A = g_wqg tile jj, B = [xq(s) | hq(s)]; writes buf (s+1)%3.
__device__ void gates_dev(int s, int jj, char* sbuf) {
    const int tid = threadIdx.x;
    const int w = tid >> 5, lane = tid & 31;
    const uint32_t sb = su32(sbuf);
    const char* xqb = (const char*)(g_xq + (size_t)s * BB * EE);
    const char* hqb = (const char*)g_hq3[s % 3];
    const int out = (s + 1) % 3;
    const char* wbase = (const char*)(g_wqg + (size_t)jj * 128 * KK);

    const int arow[4] = { (tid + 0) >> 3, (tid + 256) >> 3, (tid + 512) >> 3, (tid + 768) >> 3 };
    const int ac = tid & 7;
    const int brow = tid >> 3, bc = tid & 7;
    uint32_t dA[4];
    #pragma unroll
    for (int i = 0; i < 4; i++) dA[i] = SWZ(arow[i] * 128 + ac * 16);
    const uint32_t dB = 16384u + SWZ(brow * 128 + bc * 16);

    #define GISSUE(st, ch) do { \
        uint32_t base = sb + (st) * STAGE; \
        _Pragma("unroll") \
        for (int i = 0; i < 4; i++) \
            cpa16(base + dA[i], wbase + (size_t)arow[i] * KK + (ch) * 128 + ac * 16); \
        const char* bp = ((ch) < 4) ? (xqb + (size_t)brow * EE + (ch) * 128 + bc * 16) \
                                    : (hqb + (size_t)brow * HH + ((ch) - 4) * 128 + bc * 16); \
        cpa16(base + dB, bp); \
        CPA_COMMIT(); \
    } while (0)

    GISSUE(0, 0);
    GISSUE(1, 1);

    int c[16];
    #pragma unroll
    for (int i = 0; i < 16; i++) c[i] = 0;

    const int lr = lane & 15, lcs = (lane >> 4) << 3;
    const int bn = (lane & 7) + ((lane >> 4) << 3);
    const int bko = ((lane >> 3) & 1) << 3;

    for (int ch = 0; ch < GCH; ch++) {
        if (ch == GCH - 1) CPA_WAIT0(); else CPA_WAIT1();
        __syncthreads();
        if (ch < GCH - 2) GISSUE((ch + 2) % 3, ch + 2);
        uint32_t sA = sb + (ch % 3) * STAGE;
        uint32_t sB = sA + 16384u;
        #pragma unroll
        for (int s4 = 0; s4 < 4; s4++) {
            uint32_t a[4], b01[4], b23[4];
            ldm_x4(a,   sA + SWZ((w * 16 + lr) * 128 + (s4 * 16 + lcs) * 2));
            ldm_x4(b01, sB + SWZ(bn * 128 + (s4 * 16 + bko) * 2));
            ldm_x4(b23, sB + SWZ((bn + 16) * 128 + (s4 * 16 + bko) * 2));
            imma16832(c + 0,  a, b01 + 0);
            imma16832(c + 4,  a, b01 + 2);
            imma16832(c + 8,  a, b23 + 0);
            imma16832(c + 12, a, b23 + 2);
        }
    }
    #undef GISSUE
    __syncthreads();

    float* sl = (float*)sbuf;   // [128][33]
    {
        int r0 = w * 16 + (lane >> 2);
        float s0 = g_sg[jj * 128 + r0],     bb0 = g_biasp[jj * 128 + r0];
        float s1 = g_sg[jj * 128 + r0 + 8], bb1 = g_biasp[jj * 128 + r0 + 8];
        #pragma unroll
        for (int g = 0; g < 4; g++) {
            int col = g * 8 + 2 * (lane & 3);
            sl[r0 * 33 + col]           = s0 * (float)c[g * 4 + 0] + bb0;
            sl[r0 * 33 + col + 1]       = s0 * (float)c[g * 4 + 1] + bb0;
            sl[(r0 + 8) * 33 + col]     = s1 * (float)c[g * 4 + 2] + bb1;
            sl[(r0 + 8) * 33 + col + 1] = s1 * (float)c[g * 4 + 3] + bb1;
        }
    }
    __syncthreads();
    {
        int hu = tid >> 3;
        int b0 = (tid & 7) * 4;
        int k = jj * 32 + hu;
        #pragma unroll
        for (int q = 0; q < 4; q++) {
            int b = b0 + q;
            float ig = sl[hu * 33 + b];
            float fg = sl[(32 + hu) * 33 + b];
            float gg = sl[(64 + hu) * 33 + b];
            float og = sl[(96 + hu) * 33 + b];
            float si = 1.f / (1.f + expf(-ig));
            float sf = 1.f / (1.f + expf(-fg));
            float so = 1.f / (1.f + expf(-og));
            float cn = sf * g_c[k * BB + b] + si * tanhf(gg);
            g_c[k * BB + b] = cn;
            float h = so * tanhf(cn);
            g_h3[out][k * BB + b] = h;
            g_hq3[out][b * HH + k] = q8(h * 127.f);
        }
    }
}

// ---------------- logits int8 GEMM + partial LSE ----------------
__device__ void logits_dev(const float* __restrict__ b_out, int t, char* sbuf,
                           float (*redM)[32], float (*redS)[32]) {
    const int tid = threadIdx.x;
    const int w = tid >> 5, lane = tid & 31;
    const int v0 = blockIdx.x * 128;
    const uint32_t sb = su32(sbuf);
    const char* wbase = (const char*)(g_wq + (size_t)v0 * HH);
    const char* hqb = (const char*)g_hq3[(t + 1) % 3];

    const int arow[4] = { (tid + 0) >> 3, (tid + 256) >> 3, (tid + 512) >> 3, (tid + 768) >> 3 };
    const int ac = tid & 7;
    const int brow = tid >> 3, bc = tid & 7;
    uint32_t dA[4];
    #pragma unroll
    for (int i = 0; i < 4; i++) dA[i] = SWZ(arow[i] * 128 + ac * 16);
    const uint32_t dB = 16384u + SWZ(brow * 128 + bc * 16);

    #define LISSUE(st, ch) do { \
        uint32_t base = sb + (st) * STAGE; \
        _Pragma("unroll") \
        for (int i = 0; i < 4; i++) \
            cpa16(base + dA[i], wbase + (size_t)arow[i] * HH + (ch) * 128 + ac * 16); \
        cpa16(base + dB, hqb + (size_t)brow * HH + (ch) * 128 + bc * 16); \
        CPA_COMMIT(); \
    } while (0)

    LISSUE(0, 0);
    LISSUE(1, 1);

    int c[16];
    #pragma unroll
    for (int i = 0; i < 16; i++) c[i] = 0;

    const int lr = lane & 15, lcs = (lane >> 4) << 3;
    const int bn = (lane & 7) + ((lane >> 4) << 3);
    const int bko = ((lane >> 3) & 1) << 3;

    for (int ch = 0; ch < LCH; ch++) {
        if (ch == LCH - 1) CPA_WAIT0(); else CPA_WAIT1();
        __syncthreads();
        if (ch < LCH - 2) LISSUE((ch + 2) % 3, ch + 2);
        uint32_t sA = sb + (ch % 3) * STAGE;
        uint32_t sB = sA + 16384u;
        #pragma unroll
        for (int s4 = 0; s4 < 4; s4++) {
            uint32_t a[4], b01[4], b23[4];
            ldm_x4(a,   sA + SWZ((w * 16 + lr) * 128 + (s4 * 16 + lcs) * 2));
            ldm_x4(b01, sB + SWZ(bn * 128 + (s4 * 16 + bko) * 2));
            ldm_x4(b23, sB + SWZ((bn + 16) * 128 + (s4 * 16 + bko) * 2));
            imma16832(c + 0,  a, b01 + 0);
            imma16832(c + 4,  a, b01 + 2);
            imma16832(c + 8,  a, b23 + 0);
            imma16832(c + 12, a, b23 + 2);
        }
    }
    #undef LISSUE
    __syncthreads();

    float* sl = (float*)sbuf;
    {
        int r0 = w * 16 + (lane >> 2);
        float f0 = g_fsw[v0 + r0],     bb0 = b_out[v0 + r0];
        float f1 = g_fsw[v0 + r0 + 8], bb1 = b_out[v0 + r0 + 8];
        #pragma unroll
        for (int g = 0; g < 4; g++) {
            int col = g * 8 + 2 * (lane & 3);
            sl[r0 * 33 + col]           = f0 * (float)c[g * 4 + 0] + bb0;
            sl[r0 * 33 + col + 1]       = f0 * (float)c[g * 4 + 1] + bb0;
            sl[(r0 + 8) * 33 + col]     = f1 * (float)c[g * 4 + 2] + bb1;
            sl[(r0 + 8) * 33 + col + 1] = f1 * (float)c[g * 4 + 3] + bb1;
        }
    }
    __syncthreads();

    if (tid < 128) {
        int q = tid >> 5, b = tid & 31;
        float M = -1e30f, S = 0.f;
        #pragma unroll
        for (int r = 0; r < 32; r++) {
            float l = sl[(q * 32 + r) * 33 + b];
            if (l > M) { S = S * expf(M - l) + 1.f; M = l; }
            else       { S += expf(l - M); }
        }
        redM[q][b] = M; redS[q][b] = S;
    }
    __syncthreads();
    if (tid < 32) {
        float M = -1e30f, S = 0.f;
        #pragma unroll
        for (int q = 0; q < 4; q++) {
            float m2 = redM[q][tid], s2 = redS[q][tid];
            if (m2 > M) { S = S * expf(M - m2) + s2; M = m2; }
            else        { S += s2 * expf(m2 - M); }
        }
        g_part[t & 1][blockIdx.x * BB + tid] = make_float2(M, S);
    }
}

// ---------------- merge ----------------
__device__ void merge_dev(const int* __restrict__ indices, const float* __restrict__ W_out,
                          const float* __restrict__ b_out, int tau, float* nll) {
    const int tid = threadIdx.x;
    const int wid = tid >> 5, l = tid & 31;
    const float2* part = g_part[tau & 1];
    const float* hfp = g_h3[(tau + 1) % 3];

    for (int b = wid; b < 32; b += 8) {
        float M = -1e30f;
        for (int c = l; c < NCHUNK; c += 32) M = fmaxf(M, part[c * BB + b].x);
        #pragma unroll
        for (int o = 16; o; o >>= 1) M = fmaxf(M, __shfl_xor_sync(0xFFFFFFFFu, M, o));
        float S = 0.f;
        for (int c = l; c < NCHUNK; c += 32) {
            float2 p = part[c * BB + b];
            S += p.y * expf(p.x - M);
        }
        #pragma unroll
        for (int o = 16; o; o >>= 1) S += __shfl_xor_sync(0xFFFFFFFFu, S, o);
        int tgt = indices[(tau + 1) * BB + b];
        float z = 0.f;
        for (int e = l; e < HH; e += 32) z += hfp[e * BB + b] * W_out[(size_t)tgt * HH + e];
        #pragma unroll
        for (int o = 16; o; o >>= 1) z += __shfl_xor_sync(0xFFFFFFFFu, z, o);
        if (l == 0) nll[b] = (tgt != 0) ? (logf(S) + M - (z + b_out[tgt])) : 0.f;
    }
    __syncthreads();
    if (tid == 0) {
        float acc = g_loss;
        #pragma unroll
        for (int b = 0; b < 32; b++) acc += nll[b];
        g_loss = acc;
    }
}

// ---------------- per-step fused kernel ----------------
// t in [-1, 127]. CTAs 0-249: logits(t) [0<=t<=126]. 250-281: gates(s=t+1) [s<=126].
// 282: merge(t-1) [1<=t<=127].
__global__ void __launch_bounds__(256) k_step(const int* __restrict__ indices,
                                              const float* __restrict__ W_out,
                                              const float* __restrict__ b_out, int t) {
    extern __shared__ char sbuf[];
    __shared__ float redM[4][32], redS[4][32];
    __shared__ float nll[32];
    int bid = blockIdx.x;
    if (bid < NCHUNK) {
        if (t >= 0 && t <= TT - 2) logits_dev(b_out, t, sbuf, redM, redS);
    } else if (bid < NCHUNK + 32) {
        int s = t + 1;
        if (s >= 0 && s <= TT - 2) gates_dev(s, bid - NCHUNK, sbuf);
    } else {
        if (t >= 1 && t <= TT - 1) merge_dev(indices, W_out, b_out, t - 1, nll);
    }
}

__global__ void k_out(float* out, int n) {
    int i = blockIdx.x * blockDim.x + threadIdx.x;
    if (i < n) out[i] = (i == 0) ? g_loss : 0.f;
}

// ---------------- launch ----------------
extern "C" void kernel_launch(void* const* d_in, const int* in_sizes, int n_in,
                              void* d_out, int out_size) {
    const int*   indices = (const int*)d_in[0];
    const float* emb     = (const float*)d_in[1];
    const float* W_ih    = (const float*)d_in[2];
    const float* W_hh    = (const float*)d_in[3];
    const float* b_ih    = (const float*)d_in[4];
    const float* b_hh    = (const float*)d_in[5];
    const float* W_out   = (const float*)d_in[6];
    const float* b_out   = (const float*)d_in[7];
    const float* h0      = (const float*)d_in[8];
    const float* c0      = (const float*)d_in[9];

    cudaFuncSetAttribute(k_step, cudaFuncAttributeMaxDynamicSharedMemorySize, 3 * STAGE);

    k_setup1<<<VV / 8, 256>>>(W_out, emb);
    k_setup2<<<GG / 8, 256>>>(W_ih, W_hh, b_ih, b_hh);
    k_setup3<<<508 + 128, 256>>>(indices, emb, h0, c0);

    for (int t = -1; t < TT; t++)
        k_step<<<NCHUNK + 32 + 1, 256, 3 * STAGE>>>(indices, W_out, b_out, t);
    k_out<<<(out_size + 255) / 256, 256>>>((float*)d_out, out_size);
}

// round 10
// speedup vs baseline: 1.2815x; 1.0987x over previous
#include <cuda_runtime.h>
#include <cuda_bf16.h>
#include <stdint.h>
#include <stddef.h>
#include <math.h>

#define TT 128
#define BB 32
#define VV 32000
#define EE 512
#define HH 1024
#define KK 1536
#define GG 4096
#define NCHUNK 250       // logits chunks of 128 vocab rows
#define STAGE 20480      // stage bytes: A 16K + B 4K
#define LCH 8            // logits K-chunks of 128 int8
#define GCH 12           // gates K-chunks of 128 int8
#define SP_OFF 24576     // int partial buffer offset in sbuf

// ---------------- scratch ----------------
__device__ __align__(16) float g_h3[3][HH * BB];          // h fp32 [k][b]
__device__ __align__(16) signed char g_hq3[3][BB * HH];   // h int8 [b][k], scale 1/127
__device__ __align__(16) float g_c[HH * BB];              // c[k][b]
__device__ __align__(16) signed char g_wq[(size_t)VV * HH];   // W_out int8 (32MB)
__device__ __align__(16) float g_fsw[VV];                 // rowmax/(127*127)
__device__ __align__(16) signed char g_wqg[(size_t)GG * KK];  // gates W int8, permuted+col-scaled
__device__ __align__(16) float g_sg[GG];                  // per-row scale
__device__ __align__(16) float g_biasp[GG];               // permuted b_ih+b_hh
__device__ __align__(16) signed char g_xq[(TT - 1) * BB * EE]; // x int8, all steps (2MB)
__device__ unsigned g_xmax = 0u;                          // max relu(emb) as uint bits
__device__ float2 g_part[2][NCHUNK * BB];
__device__ float g_loss;

// ---------------- helpers ----------------
__device__ __forceinline__ uint32_t su32(const void* p) {
    uint32_t a;
    asm("{ .reg .u64 t; cvta.to.shared.u64 t, %1; cvt.u32.u64 %0, t; }" : "=r"(a) : "l"(p));
    return a;
}
#define SWZ(o) ((o) ^ (((o) >> 3) & 0x70))

__device__ __forceinline__ void ldm_x4(uint32_t* r, uint32_t addr) {
    asm volatile("ldmatrix.sync.aligned.m8n8.x4.shared.b16 {%0,%1,%2,%3}, [%4];"
                 : "=r"(r[0]), "=r"(r[1]), "=r"(r[2]), "=r"(r[3]) : "r"(addr));
}
__device__ __forceinline__ void imma16832(int* c, const uint32_t* a, const uint32_t* b) {
    asm volatile("mma.sync.aligned.m16n8k32.row.col.s32.s8.s8.s32 "
                 "{%0,%1,%2,%3}, {%4,%5,%6,%7}, {%8,%9}, {%0,%1,%2,%3};"
                 : "+r"(c[0]), "+r"(c[1]), "+r"(c[2]), "+r"(c[3])
                 : "r"(a[0]), "r"(a[1]), "r"(a[2]), "r"(a[3]), "r"(b[0]), "r"(b[1]));
}
__device__ __forceinline__ void cpa16(uint32_t dst, const void* src) {
    asm volatile("cp.async.cg.shared.global [%0], [%1], 16;" :: "r"(dst), "l"(src) : "memory");
}
#define CPA_COMMIT() asm volatile("cp.async.commit_group;" ::: "memory")
#define CPA_WAIT1()  asm volatile("cp.async.wait_group 1;" ::: "memory")
#define CPA_WAIT0()  asm volatile("cp.async.wait_group 0;" ::: "memory")

__device__ __forceinline__ signed char q8(float v) {
    int x = __float2int_rn(v);
    x = x > 127 ? 127 : (x < -127 ? -127 : x);
    return (signed char)x;
}

// ---------------- setup 1: W_out -> int8 per-row; emb max ----------------
__global__ void k_setup1(const float* __restrict__ W, const float* __restrict__ emb) {
    int wid = blockIdx.x * 8 + (threadIdx.x >> 5);
    int lane = threadIdx.x & 31;
    const float* row = W + (size_t)wid * HH;
    float m = 0.f;
    #pragma unroll
    for (int i = 0; i < 32; i++) m = fmaxf(m, fabsf(row[lane + 32 * i]));
    #pragma unroll
    for (int o = 16; o; o >>= 1) m = fmaxf(m, __shfl_xor_sync(0xFFFFFFFFu, m, o));
    float inv = (m > 1e-30f) ? 127.f / m : 0.f;
    if (lane == 0) g_fsw[wid] = m / (127.f * 127.f);
    signed char* dst = g_wq + (size_t)wid * HH;
    #pragma unroll
    for (int i = 0; i < 32; i++) {
        int k = lane + 32 * i;
        dst[k] = q8(row[k] * inv);
    }
    size_t gtid = (size_t)blockIdx.x * blockDim.x + threadIdx.x;
    size_t n = (size_t)VV * EE, nt = (size_t)gridDim.x * blockDim.x;
    float em = 0.f;
    for (size_t i = gtid; i < n; i += nt) em = fmaxf(em, emb[i]);
    #pragma unroll
    for (int o = 16; o; o >>= 1) em = fmaxf(em, __shfl_xor_sync(0xFFFFFFFFu, em, o));
    if (lane == 0 && em > 0.f) atomicMax(&g_xmax, __float_as_uint(em));
}

// ---------------- setup 2: gates W permute + col-scale + per-row int8 ----------------
__global__ void k_setup2(const float* __restrict__ W_ih, const float* __restrict__ W_hh,
                         const float* __restrict__ b_ih, const float* __restrict__ b_hh) {
    int id = blockIdx.x * 8 + (threadIdx.x >> 5);
    int lane = threadIdx.x & 31;
    int j = id >> 7, r = id & 127;
    int srcrow = (r >> 5) * HH + j * 32 + (r & 31);
    float s_x = __uint_as_float(g_xmax) / 127.f;
    const float sh = 1.f / 127.f;
    float m = 0.f;
    #pragma unroll
    for (int i = 0; i < 48; i++) {
        int k = lane + 32 * i;
        float w = (k < EE) ? W_ih[(size_t)srcrow * EE + k] * s_x
                           : W_hh[(size_t)srcrow * HH + (k - EE)] * sh;
        m = fmaxf(m, fabsf(w));
    }
    #pragma unroll
    for (int o = 16; o; o >>= 1) m = fmaxf(m, __shfl_xor_sync(0xFFFFFFFFu, m, o));
    float inv = (m > 1e-30f) ? 127.f / m : 0.f;
    if (lane == 0) { g_sg[id] = m / 127.f; g_biasp[id] = b_ih[srcrow] + b_hh[srcrow]; }
    signed char* dst = g_wqg + (size_t)id * KK;
    #pragma unroll
    for (int i = 0; i < 48; i++) {
        int k = lane + 32 * i;
        float w = (k < EE) ? W_ih[(size_t)srcrow * EE + k] * s_x
                           : W_hh[(size_t)srcrow * HH + (k - EE)] * sh;
        dst[k] = q8(w * inv);
    }
}

// ---------------- setup 3: x int8 for all steps + state init ----------------
__global__ void k_setup3(const int* __restrict__ indices, const float* __restrict__ emb,
                         const float* __restrict__ h0, const float* __restrict__ c0) {
    if (blockIdx.x < 508) {
        int tb = blockIdx.x * 8 + (threadIdx.x >> 5);
        int lane = threadIdx.x & 31;
        if (tb < (TT - 1) * BB) {
            int idx = indices[tb];
            float inv = 127.f / __uint_as_float(g_xmax);
            const float* e = emb + (size_t)idx * EE;
            signed char* dst = g_xq + (size_t)tb * EE;
            #pragma unroll
            for (int i = 0; i < 16; i++) {
                int k = lane + 32 * i;
                dst[k] = q8(fmaxf(e[k], 0.f) * inv);
            }
        }
    } else {
        int i = (blockIdx.x - 508) * 256 + threadIdx.x;
        if (i < HH * BB) {
            int b = i / HH, k = i % HH;
            g_h3[0][k * BB + b] = h0[i];
            g_c[k * BB + b] = c0[i];
            g_hq3[0][i] = q8(h0[i] * 127.f);
        }
        if (blockIdx.x == 508 && threadIdx.x == 0) g_loss = 0.f;
    }
}

// ---------------- shared mainloop core: K-split x2 over 16 warps ----------------
// Warp w: row group g=w>>1 (16 rows), K-half kh=w&1 (sub-tiles 2*kh, 2*kh+1).
// After NCHUNKS iterations, odd warps dump int partials; even warps add.
// Returns with even warps holding full c[16]; all threads synced.
struct WarpCoord { int g, kh, lr, lcs, bn, bko; };

__device__ __forceinline__ WarpCoord wcoord() {
    int tid = threadIdx.x;
    int w = tid >> 5, lane = tid & 31;
    WarpCoord wc;
    wc.g = w >> 1; wc.kh = w & 1;
    wc.lr = lane & 15; wc.lcs = (lane >> 4) << 3;
    wc.bn = (lane & 7) + ((lane >> 4) << 3);
    wc.bko = ((lane >> 3) & 1) << 3;
    return wc;
}

__device__ __forceinline__ void mma_chunk(const WarpCoord& wc, uint32_t sA, uint32_t sB, int* c) {
    #pragma unroll
    for (int s4 = 0; s4 < 2; s4++) {
        int s = wc.kh * 2 + s4;
        uint32_t a[4], b01[4], b23[4];
        ldm_x4(a,   sA + SWZ((wc.g * 16 + wc.lr) * 128 + (s * 16 + wc.lcs) * 2));
        ldm_x4(b01, sB + SWZ(wc.bn * 128 + (s * 16 + wc.bko) * 2));
        ldm_x4(b23, sB + SWZ((wc.bn + 16) * 128 + (s * 16 + wc.bko) * 2));
        imma16832(c + 0,  a, b01 + 0);
        imma16832(c + 4,  a, b01 + 2);
        imma16832(c + 8,  a, b23 + 0);
        imma16832(c + 12, a, b23 + 2);
    }
}

__device__ __forceinline__ void ksplit_reduce(const WarpCoord& wc, char* sbuf, int* c) {
    int lane = threadIdx.x & 31;
    int* sp = (int*)(sbuf + SP_OFF);   // [8][32][17]
    __syncthreads();
    if (wc.kh == 1) {
        #pragma unroll
        for (int i = 0; i < 16; i++) sp[(wc.g * 32 + lane) * 17 + i] = c[i];
    }
    __syncthreads();
    if (wc.kh == 0) {
        #pragma unroll
        for (int i = 0; i < 16; i++) c[i] += sp[(wc.g * 32 + lane) * 17 + i];
    }
}

// ---------------- gates int8 GEMM + LSTM (512 threads) ----------------
__device__ void gates_dev(int s, int jj, char* sbuf) {
    const int tid = threadIdx.x;
    const int lane = tid & 31;
    const uint32_t sb = su32(sbuf);
    const char* xqb = (const char*)(g_xq + (size_t)s * BB * EE);
    const char* hqb = (const char*)g_hq3[s % 3];
    const int out = (s + 1) % 3;
    const char* wbase = (const char*)(g_wqg + (size_t)jj * 128 * KK);

    // staging: 2 A-slots per thread, 1 B-slot for tid<256
    const int ar0 = tid >> 3, ac = tid & 7;
    uint32_t dA0 = SWZ(ar0 * 128 + ac * 16);
    uint32_t dA1 = SWZ((ar0 + 64) * 128 + ac * 16);
    const int brow = (tid & 255) >> 3, bc = tid & 7;
    const uint32_t dB = 16384u + SWZ(brow * 128 + bc * 16);
    const bool bldr = tid < 256;

    #define GISSUE(st, ch) do { \
        uint32_t base = sb + (st) * STAGE; \
        cpa16(base + dA0, wbase + (size_t)ar0 * KK + (ch) * 128 + ac * 16); \
        cpa16(base + dA1, wbase + (size_t)(ar0 + 64) * KK + (ch) * 128 + ac * 16); \
        if (bldr) { \
            const char* bp = ((ch) < 4) ? (xqb + (size_t)brow * EE + (ch) * 128 + bc * 16) \
                                        : (hqb + (size_t)brow * HH + ((ch) - 4) * 128 + bc * 16); \
            cpa16(base + dB, bp); \
        } \
        CPA_COMMIT(); \
    } while (0)

    GISSUE(0, 0);
    GISSUE(1, 1);

    int c[16];
    #pragma unroll
    for (int i = 0; i < 16; i++) c[i] = 0;
    WarpCoord wc = wcoord();

    for (int ch = 0; ch < GCH; ch++) {
        if (ch == GCH - 1) CPA_WAIT0(); else CPA_WAIT1();
        __syncthreads();
        if (ch < GCH - 2) GISSUE((ch + 2) % 3, ch + 2);
        uint32_t sA = sb + (ch % 3) * STAGE;
        mma_chunk(wc, sA, sA + 16384u, c);
    }
    #undef GISSUE

    ksplit_reduce(wc, sbuf, c);
    __syncthreads();

    float* sl = (float*)sbuf;   // [128][33]
    if (wc.kh == 0) {
        int r0 = wc.g * 16 + (lane >> 2);
        float s0 = g_sg[jj * 128 + r0],     bb0 = g_biasp[jj * 128 + r0];
        float s1 = g_sg[jj * 128 + r0 + 8], bb1 = g_biasp[jj * 128 + r0 + 8];
        #pragma unroll
        for (int g = 0; g < 4; g++) {
            int col = g * 8 + 2 * (lane & 3);
            sl[r0 * 33 + col]           = s0 * (float)c[g * 4 + 0] + bb0;
            sl[r0 * 33 + col + 1]       = s0 * (float)c[g * 4 + 1] + bb0;
            sl[(r0 + 8) * 33 + col]     = s1 * (float)c[g * 4 + 2] + bb1;
            sl[(r0 + 8) * 33 + col + 1] = s1 * (float)c[g * 4 + 3] + bb1;
        }
    }
    __syncthreads();
    {
        int hu = tid >> 4;              // 0..31
        int b0 = (tid & 15) * 2;        // 2 batches
        int k = jj * 32 + hu;
        #pragma unroll
        for (int q = 0; q < 2; q++) {
            int b = b0 + q;
            float ig = sl[hu * 33 + b];
            float fg = sl[(32 + hu) * 33 + b];
            float gg = sl[(64 + hu) * 33 + b];
            float og = sl[(96 + hu) * 33 + b];
            float si = 1.f / (1.f + expf(-ig));
            float sf = 1.f / (1.f + expf(-fg));
            float so = 1.f / (1.f + expf(-og));
            float cn = sf * g_c[k * BB + b] + si * tanhf(gg);
            g_c[k * BB + b] = cn;
            float h = so * tanhf(cn);
            g_h3[out][k * BB + b] = h;
            g_hq3[out][b * HH + k] = q8(h * 127.f);
        }
    }
}

// ---------------- logits int8 GEMM + partial LSE (512 threads) ----------------
__device__ void logits_dev(const float* __restrict__ b_out, int t, char* sbuf,
                           float (*redM)[32], float (*redS)[32]) {
    const int tid = threadIdx.x;
    const int lane = tid & 31;
    const int v0 = blockIdx.x * 128;
    const uint32_t sb = su32(sbuf);
    const char* wbase = (const char*)(g_wq + (size_t)v0 * HH);
    const char* hqb = (const char*)g_hq3[(t + 1) % 3];

    const int ar0 = tid >> 3, ac = tid & 7;
    uint32_t dA0 = SWZ(ar0 * 128 + ac * 16);
    uint32_t dA1 = SWZ((ar0 + 64) * 128 + ac * 16);
    const int brow = (tid & 255) >> 3, bc = tid & 7;
    const uint32_t dB = 16384u + SWZ(brow * 128 + bc * 16);
    const bool bldr = tid < 256;

    #define LISSUE(st, ch) do { \
        uint32_t base = sb + (st) * STAGE; \
        cpa16(base + dA0, wbase + (size_t)ar0 * HH + (ch) * 128 + ac * 16); \
        cpa16(base + dA1, wbase + (size_t)(ar0 + 64) * HH + (ch) * 128 + ac * 16); \
        if (bldr) cpa16(base + dB, hqb + (size_t)brow * HH + (ch) * 128 + bc * 16); \
        CPA_COMMIT(); \
    } while (0)

    LISSUE(0, 0);
    LISSUE(1, 1);

    int c[16];
    #pragma unroll
    for (int i = 0; i < 16; i++) c[i] = 0;
    WarpCoord wc = wcoord();

    for (int ch = 0; ch < LCH; ch++) {
        if (ch == LCH - 1) CPA_WAIT0(); else CPA_WAIT1();
        __syncthreads();
        if (ch < LCH - 2) LISSUE((ch + 2) % 3, ch + 2);
        uint32_t sA = sb + (ch % 3) * STAGE;
        mma_chunk(wc, sA, sA + 16384u, c);
    }
    #undef LISSUE

    ksplit_reduce(wc, sbuf, c);
    __syncthreads();

    float* sl = (float*)sbuf;
    if (wc.kh == 0) {
        int r0 = wc.g * 16 + (lane >> 2);
        float f0 = g_fsw[v0 + r0],     bb0 = b_out[v0 + r0];
        float f1 = g_fsw[v0 + r0 + 8], bb1 = b_out[v0 + r0 + 8];
        #pragma unroll
        for (int g = 0; g < 4; g++) {
            int col = g * 8 + 2 * (lane & 3);
            sl[r0 * 33 + col]           = f0 * (float)c[g * 4 + 0] + bb0;
            sl[r0 * 33 + col + 1]       = f0 * (float)c[g * 4 + 1] + bb0;
            sl[(r0 + 8) * 33 + col]     = f1 * (float)c[g * 4 + 2] + bb1;
            sl[(r0 + 8) * 33 + col + 1] = f1 * (float)c[g * 4 + 3] + bb1;
        }
    }
    __syncthreads();

    if (tid < 128) {
        int q = tid >> 5, b = tid & 31;
        float M = -1e30f, S = 0.f;
        #pragma unroll
        for (int r = 0; r < 32; r++) {
            float l = sl[(q * 32 + r) * 33 + b];
            if (l > M) { S = S * expf(M - l) + 1.f; M = l; }
            else       { S += expf(l - M); }
        }
        redM[q][b] = M; redS[q][b] = S;
    }
    __syncthreads();
    if (tid < 32) {
        float M = -1e30f, S = 0.f;
        #pragma unroll
        for (int q = 0; q < 4; q++) {
            float m2 = redM[q][tid], s2 = redS[q][tid];
            if (m2 > M) { S = S * expf(M - m2) + s2; M = m2; }
            else        { S += s2 * expf(m2 - M); }
        }
        g_part[t & 1][blockIdx.x * BB + tid] = make_float2(M, S);
    }
}

// ---------------- merge (512 threads) ----------------
__device__ void merge_dev(const int* __restrict__ indices, const float* __restrict__ W_out,
                          const float* __restrict__ b_out, int tau, float* nll) {
    const int tid = threadIdx.x;
    const int wid = tid >> 5, l = tid & 31;
    const float2* part = g_part[tau & 1];
    const float* hfp = g_h3[(tau + 1) % 3];

    for (int b = wid; b < 32; b += 16) {
        float M = -1e30f;
        for (int c = l; c < NCHUNK; c += 32) M = fmaxf(M, part[c * BB + b].x);
        #pragma unroll
        for (int o = 16; o; o >>= 1) M = fmaxf(M, __shfl_xor_sync(0xFFFFFFFFu, M, o));
        float S = 0.f;
        for (int c = l; c < NCHUNK; c += 32) {
            float2 p = part[c * BB + b];
            S += p.y * expf(p.x - M);
        }
        #pragma unroll
        for (int o = 16; o; o >>= 1) S += __shfl_xor_sync(0xFFFFFFFFu, S, o);
        int tgt = indices[(tau + 1) * BB + b];
        float z = 0.f;
        for (int e = l; e < HH; e += 32) z += hfp[e * BB + b] * W_out[(size_t)tgt * HH + e];
        #pragma unroll
        for (int o = 16; o; o >>= 1) z += __shfl_xor_sync(0xFFFFFFFFu, z, o);
        if (l == 0) nll[b] = (tgt != 0) ? (logf(S) + M - (z + b_out[tgt])) : 0.f;
    }
    __syncthreads();
    if (tid == 0) {
        float acc = g_loss;
        #pragma unroll
        for (int b = 0; b < 32; b++) acc += nll[b];
        g_loss = acc;
    }
}

// ---------------- per-step fused kernel ----------------
__global__ void __launch_bounds__(512) k_step(const int* __restrict__ indices,
                                              const float* __restrict__ W_out,
                                              const float* __restrict__ b_out, int t) {
    extern __shared__ char sbuf[];
    __shared__ float redM[4][32], redS[4][32];
    __shared__ float nll[32];
    int bid = blockIdx.x;
    if (bid < NCHUNK) {
        if (t >= 0 && t <= TT - 2) logits_dev(b_out, t, sbuf, redM, redS);
    } else if (bid < NCHUNK + 32) {
        int s = t + 1;
        if (s >= 0 && s <= TT - 2) gates_dev(s, bid - NCHUNK, sbuf);
    } else {
        if (t >= 1 && t <= TT - 1) merge_dev(indices, W_out, b_out, t - 1, nll);
    }
}

__global__ void k_out(float* out, int n) {
    int i = blockIdx.x * blockDim.x + threadIdx.x;
    if (i < n) out[i] = (i == 0) ? g_loss : 0.f;
}

// ---------------- launch ----------------
extern "C" void kernel_launch(void* const* d_in, const int* in_sizes, int n_in,
                              void* d_out, int out_size) {
    const int*   indices = (const int*)d_in[0];
    const float* emb     = (const float*)d_in[1];
    const float* W_ih    = (const float*)d_in[2];
    const float* W_hh    = (const float*)d_in[3];
    const float* b_ih    = (const float*)d_in[4];
    const float* b_hh    = (const float*)d_in[5];
    const float* W_out   = (const float*)d_in[6];
    const float* b_out   = (const float*)d_in[7];
    const float* h0      = (const float*)d_in[8];
    const float* c0      = (const float*)d_in[9];

    cudaFuncSetAttribute(k_step, cudaFuncAttributeMaxDynamicSharedMemorySize, 3 * STAGE);

    k_setup1<<<VV / 8, 256>>>(W_out, emb);
    k_setup2<<<GG / 8, 256>>>(W_ih, W_hh, b_ih, b_hh);
    k_setup3<<<508 + 128, 256>>>(indices, emb, h0, c0);

    for (int t = -1; t < TT; t++)
        k_step<<<NCHUNK + 32 + 1, 512, 3 * STAGE>>>(indices, W_out, b_out, t);
    k_out<<<(out_size + 255) / 256, 256>>>((float*)d_out, out_size);
}